// round 4
// baseline (speedup 1.0000x reference)
#include <cuda_runtime.h>
#include <math.h>

#define NROW 8192
#define NE   262144

// ---------------- scratch (static device arrays; no allocation) ----------------
__device__ __align__(16) float g_t[NROW * 256];   // x@W1+b1
__device__ __align__(16) float g_h[NROW * 256];   // tanh(spmm(t))
__device__ __align__(16) float g_g[NROW * 128];   // h@[Wmu|Wls]+b
__device__ __align__(16) float g_z[NROW * 64];
__device__ int   g_counts[NROW];
__device__ int   g_cursor[NROW];
__device__ int   g_rowptr[NROW + 1];
__device__ int   g_cols[NE];
__device__ __align__(16) float g_wts[NE];

// ---------------- packed f32x2 helpers (bit-exact fp32, 2x FFMA rate) ----------
__device__ __forceinline__ unsigned long long dup2(float x) {
    unsigned long long u;
    asm("mov.b64 %0, {%1, %1};" : "=l"(u) : "f"(x));
    return u;
}
__device__ __forceinline__ void ffma2(unsigned long long& acc, unsigned long long a,
                                      unsigned long long b) {
    asm("fma.rn.f32x2 %0, %1, %2, %0;" : "+l"(acc) : "l"(a), "l"(b));
}
__device__ __forceinline__ float2 unpack2(unsigned long long u) {
    float2 v;
    asm("mov.b64 {%0, %1}, %2;" : "=f"(v.x), "=f"(v.y) : "l"(u));
    return v;
}

// ---------------- CSR build ----------------
__global__ void k_zero() {
    int i = blockIdx.x * 256 + threadIdx.x;
    if (i < NROW) g_counts[i] = 0;
    else g_cursor[i - NROW] = 0;
}

__global__ void k_count(const int* __restrict__ src) {
    int i = blockIdx.x * 256 + threadIdx.x;
    if (i < NE) atomicAdd(&g_counts[src[i]], 1);
}

__global__ void k_scan() {  // one block, 1024 threads, 8 counts each
    __shared__ int sh[1024];
    int tid = threadIdx.x;
    int c[8]; int s = 0;
#pragma unroll
    for (int i = 0; i < 8; i++) { c[i] = g_counts[tid * 8 + i]; s += c[i]; }
    sh[tid] = s;
    __syncthreads();
    for (int off = 1; off < 1024; off <<= 1) {
        int v = (tid >= off) ? sh[tid - off] : 0;
        __syncthreads();
        sh[tid] += v;
        __syncthreads();
    }
    int base = sh[tid] - s;  // exclusive prefix
#pragma unroll
    for (int i = 0; i < 8; i++) { g_rowptr[tid * 8 + i] = base; base += c[i]; }
    if (tid == 1023) g_rowptr[NROW] = sh[1023];
}

__global__ void k_scatter(const int* __restrict__ src, const int* __restrict__ dst,
                          const float* __restrict__ w) {
    int i = blockIdx.x * 256 + threadIdx.x;
    if (i < NE) {
        int r = src[i];
        int pos = g_rowptr[r] + atomicAdd(&g_cursor[r], 1);
        g_cols[pos] = dst[i];
        g_wts[pos]  = w[i];
    }
}

// ---------------- GEMM1: g_t = x[8192,512] @ W1[512,256] + b1 ----------------
// 128x64 tile, 256 threads, 8x4 per-thread micro-tile (row pairs packed f32x2)
__global__ __launch_bounds__(256) void k_gemm1(const float* __restrict__ x,
                                               const float* __restrict__ W1,
                                               const float* __restrict__ b1) {
    __shared__ float As[16 * 128];  // transposed A tile, swizzled
    __shared__ float Bs[16 * 64];
    const int bm = blockIdx.y, bn = blockIdx.x;
    const int tid = threadIdx.x;
    const int ty = tid >> 4, tx = tid & 15;
    const int row0 = ty * 8, col0 = tx * 4;

    unsigned long long acc[4][4];
    {
        float4 bv = *(const float4*)(b1 + bn * 64 + col0);
        unsigned long long ix = dup2(bv.x), iy = dup2(bv.y), iz = dup2(bv.z), iw = dup2(bv.w);
#pragma unroll
        for (int p = 0; p < 4; p++) { acc[p][0] = ix; acc[p][1] = iy; acc[p][2] = iz; acc[p][3] = iw; }
    }

    for (int kt = 0; kt < 32; kt++) {
#pragma unroll
        for (int pass = 0; pass < 2; pass++) {
            int idx = tid + pass * 256;
            int ar = idx >> 2;          // 0..127
            int kq = idx & 3;
            float4 v = *(const float4*)(x + (size_t)(bm * 128 + ar) * 512 + kt * 16 + kq * 4);
            int rs = ar ^ (kq << 3);    // swizzle in bits 3..4 (outside 8-row group)
            As[(kq * 4 + 0) * 128 + rs] = v.x;
            As[(kq * 4 + 1) * 128 + rs] = v.y;
            As[(kq * 4 + 2) * 128 + rs] = v.z;
            As[(kq * 4 + 3) * 128 + rs] = v.w;
        }
        {
            int kr = tid >> 4, cq = tid & 15;
            *(float4*)&Bs[kr * 64 + cq * 4] =
                *(const float4*)(W1 + (size_t)(kt * 16 + kr) * 256 + bn * 64 + cq * 4);
        }
        __syncthreads();
#pragma unroll
        for (int k = 0; k < 16; k++) {
            const float* ab = &As[k * 128 + (row0 ^ ((k >> 2) << 3))];
            unsigned long long a0 = *(const unsigned long long*)(ab + 0);
            unsigned long long a1 = *(const unsigned long long*)(ab + 2);
            unsigned long long a2 = *(const unsigned long long*)(ab + 4);
            unsigned long long a3 = *(const unsigned long long*)(ab + 6);
            float4 b = *(const float4*)&Bs[k * 64 + col0];
            unsigned long long bx = dup2(b.x), by = dup2(b.y), bz = dup2(b.z), bw = dup2(b.w);
            ffma2(acc[0][0], a0, bx); ffma2(acc[0][1], a0, by); ffma2(acc[0][2], a0, bz); ffma2(acc[0][3], a0, bw);
            ffma2(acc[1][0], a1, bx); ffma2(acc[1][1], a1, by); ffma2(acc[1][2], a1, bz); ffma2(acc[1][3], a1, bw);
            ffma2(acc[2][0], a2, bx); ffma2(acc[2][1], a2, by); ffma2(acc[2][2], a2, bz); ffma2(acc[2][3], a2, bw);
            ffma2(acc[3][0], a3, bx); ffma2(acc[3][1], a3, by); ffma2(acc[3][2], a3, bz); ffma2(acc[3][3], a3, bw);
        }
        __syncthreads();
    }
    float* Cp = g_t + (size_t)(bm * 128 + row0) * 256 + bn * 64 + col0;
#pragma unroll
    for (int p = 0; p < 4; p++) {
        float2 t0 = unpack2(acc[p][0]), t1 = unpack2(acc[p][1]);
        float2 t2 = unpack2(acc[p][2]), t3 = unpack2(acc[p][3]);
        *(float4*)(Cp + (size_t)(2 * p) * 256)     = make_float4(t0.x, t1.x, t2.x, t3.x);
        *(float4*)(Cp + (size_t)(2 * p + 1) * 256) = make_float4(t0.y, t1.y, t2.y, t3.y);
    }
}

// ---------------- GEMM2: g_g = g_h[8192,256] @ [Wmu|Wls][256,128] + [bmu|bls] ----
__global__ __launch_bounds__(256) void k_gemm2(const float* __restrict__ Wmu,
                                               const float* __restrict__ bmu,
                                               const float* __restrict__ Wls,
                                               const float* __restrict__ bls) {
    __shared__ float As[16 * 128];
    __shared__ float Bs[16 * 64];
    const int bm = blockIdx.y, bn = blockIdx.x;  // bn=0 -> mu head, bn=1 -> ls head
    const float* W = (bn == 0) ? Wmu : Wls;
    const float* bb = (bn == 0) ? bmu : bls;
    const int tid = threadIdx.x;
    const int ty = tid >> 4, tx = tid & 15;
    const int row0 = ty * 8, col0 = tx * 4;

    unsigned long long acc[4][4];
    {
        float4 bv = *(const float4*)(bb + col0);
        unsigned long long ix = dup2(bv.x), iy = dup2(bv.y), iz = dup2(bv.z), iw = dup2(bv.w);
#pragma unroll
        for (int p = 0; p < 4; p++) { acc[p][0] = ix; acc[p][1] = iy; acc[p][2] = iz; acc[p][3] = iw; }
    }

    for (int kt = 0; kt < 16; kt++) {
#pragma unroll
        for (int pass = 0; pass < 2; pass++) {
            int idx = tid + pass * 256;
            int ar = idx >> 2;
            int kq = idx & 3;
            float4 v = *(const float4*)(g_h + (size_t)(bm * 128 + ar) * 256 + kt * 16 + kq * 4);
            int rs = ar ^ (kq << 3);
            As[(kq * 4 + 0) * 128 + rs] = v.x;
            As[(kq * 4 + 1) * 128 + rs] = v.y;
            As[(kq * 4 + 2) * 128 + rs] = v.z;
            As[(kq * 4 + 3) * 128 + rs] = v.w;
        }
        {
            int kr = tid >> 4, cq = tid & 15;
            *(float4*)&Bs[kr * 64 + cq * 4] =
                *(const float4*)(W + (size_t)(kt * 16 + kr) * 64 + cq * 4);
        }
        __syncthreads();
#pragma unroll
        for (int k = 0; k < 16; k++) {
            const float* ab = &As[k * 128 + (row0 ^ ((k >> 2) << 3))];
            unsigned long long a0 = *(const unsigned long long*)(ab + 0);
            unsigned long long a1 = *(const unsigned long long*)(ab + 2);
            unsigned long long a2 = *(const unsigned long long*)(ab + 4);
            unsigned long long a3 = *(const unsigned long long*)(ab + 6);
            float4 b = *(const float4*)&Bs[k * 64 + col0];
            unsigned long long bx = dup2(b.x), by = dup2(b.y), bz = dup2(b.z), bw = dup2(b.w);
            ffma2(acc[0][0], a0, bx); ffma2(acc[0][1], a0, by); ffma2(acc[0][2], a0, bz); ffma2(acc[0][3], a0, bw);
            ffma2(acc[1][0], a1, bx); ffma2(acc[1][1], a1, by); ffma2(acc[1][2], a1, bz); ffma2(acc[1][3], a1, bw);
            ffma2(acc[2][0], a2, bx); ffma2(acc[2][1], a2, by); ffma2(acc[2][2], a2, bz); ffma2(acc[2][3], a2, bw);
            ffma2(acc[3][0], a3, bx); ffma2(acc[3][1], a3, by); ffma2(acc[3][2], a3, bz); ffma2(acc[3][3], a3, bw);
        }
        __syncthreads();
    }
    float* Cp = g_g + (size_t)(bm * 128 + row0) * 128 + bn * 64 + col0;
#pragma unroll
    for (int p = 0; p < 4; p++) {
        float2 t0 = unpack2(acc[p][0]), t1 = unpack2(acc[p][1]);
        float2 t2 = unpack2(acc[p][2]), t3 = unpack2(acc[p][3]);
        *(float4*)(Cp + (size_t)(2 * p) * 128)     = make_float4(t0.x, t1.x, t2.x, t3.x);
        *(float4*)(Cp + (size_t)(2 * p + 1) * 128) = make_float4(t0.y, t1.y, t2.y, t3.y);
    }
}

// ---------------- SpMM1 + tanh: g_h[r] = tanh(sum w * g_t[col]) ----------------
__global__ void k_spmm1() {  // grid 8192, block 128: one row per block, float2/thread
    int r = blockIdx.x, tid = threadIdx.x;
    int s = g_rowptr[r], e = g_rowptr[r + 1];
    const float2* T = (const float2*)g_t;
    float2 acc = make_float2(0.f, 0.f);
    int p = s;
    for (; p + 4 <= e; p += 4) {
        int   c0 = g_cols[p], c1 = g_cols[p + 1], c2 = g_cols[p + 2], c3 = g_cols[p + 3];
        float w0 = g_wts[p], w1 = g_wts[p + 1], w2 = g_wts[p + 2], w3 = g_wts[p + 3];
        float2 v0 = T[c0 * 128 + tid];
        float2 v1 = T[c1 * 128 + tid];
        float2 v2 = T[c2 * 128 + tid];
        float2 v3 = T[c3 * 128 + tid];
        acc.x = fmaf(w0, v0.x, acc.x); acc.y = fmaf(w0, v0.y, acc.y);
        acc.x = fmaf(w1, v1.x, acc.x); acc.y = fmaf(w1, v1.y, acc.y);
        acc.x = fmaf(w2, v2.x, acc.x); acc.y = fmaf(w2, v2.y, acc.y);
        acc.x = fmaf(w3, v3.x, acc.x); acc.y = fmaf(w3, v3.y, acc.y);
    }
    for (; p < e; p++) {
        int c = g_cols[p]; float w = g_wts[p];
        float2 v = T[c * 128 + tid];
        acc.x = fmaf(w, v.x, acc.x); acc.y = fmaf(w, v.y, acc.y);
    }
    ((float2*)g_h)[r * 128 + tid] = make_float2(tanhf(acc.x), tanhf(acc.y));
}

// ---------------- SpMM2 + reparameterize ----------------
__global__ void k_spmm2(const float* __restrict__ eps, float* __restrict__ oz,
                        float* __restrict__ omu, float* __restrict__ ols) {
    int r = blockIdx.x, tid = threadIdx.x;  // block 128: feature tid of [mu|ls]
    int s = g_rowptr[r], e = g_rowptr[r + 1];
    float acc = 0.f;
    int p = s;
    for (; p + 4 <= e; p += 4) {
        int   c0 = g_cols[p], c1 = g_cols[p + 1], c2 = g_cols[p + 2], c3 = g_cols[p + 3];
        float w0 = g_wts[p], w1 = g_wts[p + 1], w2 = g_wts[p + 2], w3 = g_wts[p + 3];
        float v0 = g_g[c0 * 128 + tid];
        float v1 = g_g[c1 * 128 + tid];
        float v2 = g_g[c2 * 128 + tid];
        float v3 = g_g[c3 * 128 + tid];
        acc = fmaf(w0, v0, acc); acc = fmaf(w1, v1, acc);
        acc = fmaf(w2, v2, acc); acc = fmaf(w3, v3, acc);
    }
    for (; p < e; p++) acc = fmaf(g_wts[p], g_g[g_cols[p] * 128 + tid], acc);
    __shared__ float sm[128];
    sm[tid] = acc;
    __syncthreads();
    if (tid < 64) {
        float mu = sm[tid], ls = sm[tid + 64];
        float z = fmaf(eps[r * 64 + tid], expf(ls), mu);
        omu[r * 64 + tid] = mu;
        ols[r * 64 + tid] = ls;
        oz[r * 64 + tid]  = z;
        g_z[r * 64 + tid] = z;
    }
}

// ---------------- z @ z^T (symmetric, triangular grid, mirrored write) ----------
__global__ __launch_bounds__(256, 2) void k_zzt(float* __restrict__ C) {
    extern __shared__ float sm[];
    float* As = sm;             // [64][128] transposed, swizzle row^(8*kq) (bits 3..6)
    float* Bs = sm + 64 * 128;  // [64][128] transposed, swizzle row^(4*kq) (bits 2..5)
    // triangular block index -> (bi <= bj)
    int t = blockIdx.x;
    int bi = 0;
    {
        int rem = t;
        while (rem >= 64 - bi) { rem -= 64 - bi; bi++; }
        t = bi + rem;  // bj
    }
    const int bj = t;
    const int tid = threadIdx.x;

#pragma unroll
    for (int pass = 0; pass < 8; pass++) {
        int idx = tid + pass * 256;
        int row = idx >> 4;      // 0..127
        int kq  = idx & 15;      // float4 chunk along K
        float4 va = *(const float4*)(g_z + (size_t)(bi * 128 + row) * 64 + kq * 4);
        float4 vb = *(const float4*)(g_z + (size_t)(bj * 128 + row) * 64 + kq * 4);
        int ra = row ^ (kq << 3);   // bits 3..6: preserves 8-row groups
        int rb = row ^ (kq << 2);   // bits 2..5: preserves 4-col groups
        As[(kq * 4 + 0) * 128 + ra] = va.x;
        As[(kq * 4 + 1) * 128 + ra] = va.y;
        As[(kq * 4 + 2) * 128 + ra] = va.z;
        As[(kq * 4 + 3) * 128 + ra] = va.w;
        Bs[(kq * 4 + 0) * 128 + rb] = vb.x;
        Bs[(kq * 4 + 1) * 128 + rb] = vb.y;
        Bs[(kq * 4 + 2) * 128 + rb] = vb.z;
        Bs[(kq * 4 + 3) * 128 + rb] = vb.w;
    }
    __syncthreads();

    const int ty = tid >> 4, tx = tid & 15;
    const int row0 = ty * 8, col0 = tx * 4;
    unsigned long long acc[4][8];
#pragma unroll
    for (int p = 0; p < 4; p++)
#pragma unroll
        for (int c = 0; c < 8; c++) acc[p][c] = 0ull;

#pragma unroll 8
    for (int k = 0; k < 64; k++) {
        const float* ab = &As[k * 128 + (row0 ^ ((k >> 2) << 3))];
        unsigned long long a0 = *(const unsigned long long*)(ab + 0);
        unsigned long long a1 = *(const unsigned long long*)(ab + 2);
        unsigned long long a2 = *(const unsigned long long*)(ab + 4);
        unsigned long long a3 = *(const unsigned long long*)(ab + 6);
        int cs = (k >> 2) << 2;
        float4 bA = *(const float4*)&Bs[k * 128 + (col0 ^ cs)];
        float4 bB = *(const float4*)&Bs[k * 128 + ((col0 + 64) ^ cs)];
        unsigned long long d0 = dup2(bA.x), d1 = dup2(bA.y), d2 = dup2(bA.z), d3 = dup2(bA.w);
        unsigned long long d4 = dup2(bB.x), d5 = dup2(bB.y), d6 = dup2(bB.z), d7 = dup2(bB.w);
        ffma2(acc[0][0], a0, d0); ffma2(acc[0][1], a0, d1); ffma2(acc[0][2], a0, d2); ffma2(acc[0][3], a0, d3);
        ffma2(acc[0][4], a0, d4); ffma2(acc[0][5], a0, d5); ffma2(acc[0][6], a0, d6); ffma2(acc[0][7], a0, d7);
        ffma2(acc[1][0], a1, d0); ffma2(acc[1][1], a1, d1); ffma2(acc[1][2], a1, d2); ffma2(acc[1][3], a1, d3);
        ffma2(acc[1][4], a1, d4); ffma2(acc[1][5], a1, d5); ffma2(acc[1][6], a1, d6); ffma2(acc[1][7], a1, d7);
        ffma2(acc[2][0], a2, d0); ffma2(acc[2][1], a2, d1); ffma2(acc[2][2], a2, d2); ffma2(acc[2][3], a2, d3);
        ffma2(acc[2][4], a2, d4); ffma2(acc[2][5], a2, d5); ffma2(acc[2][6], a2, d6); ffma2(acc[2][7], a2, d7);
        ffma2(acc[3][0], a3, d0); ffma2(acc[3][1], a3, d1); ffma2(acc[3][2], a3, d2); ffma2(acc[3][3], a3, d3);
        ffma2(acc[3][4], a3, d4); ffma2(acc[3][5], a3, d5); ffma2(acc[3][6], a3, d6); ffma2(acc[3][7], a3, d7);
    }

    const int gr = bi * 128 + row0;          // global row base of this thread
    const int gcA = bj * 128 + col0;         // cols 0..3
    const int gcB = bj * 128 + 64 + col0;    // cols 4..7
    // normal tile: C[gr..][gc..]
#pragma unroll
    for (int p = 0; p < 4; p++) {
        float2 t0 = unpack2(acc[p][0]), t1 = unpack2(acc[p][1]);
        float2 t2 = unpack2(acc[p][2]), t3 = unpack2(acc[p][3]);
        float2 t4 = unpack2(acc[p][4]), t5 = unpack2(acc[p][5]);
        float2 t6 = unpack2(acc[p][6]), t7 = unpack2(acc[p][7]);
        float* rlo = C + (size_t)(gr + 2 * p) * NROW;
        float* rhi = C + (size_t)(gr + 2 * p + 1) * NROW;
        *(float4*)(rlo + gcA) = make_float4(t0.x, t1.x, t2.x, t3.x);
        *(float4*)(rlo + gcB) = make_float4(t4.x, t5.x, t6.x, t7.x);
        *(float4*)(rhi + gcA) = make_float4(t0.y, t1.y, t2.y, t3.y);
        *(float4*)(rhi + gcB) = make_float4(t4.y, t5.y, t6.y, t7.y);
    }
    // mirror tile: C[col][row] — packed row-pair accs are already contiguous here
#pragma unroll
    for (int c = 0; c < 8; c++) {
        int gcol = (c < 4) ? (gcA + c) : (gcB + c - 4);
        float* col_ptr = C + (size_t)gcol * NROW + gr;
#pragma unroll
        for (int p = 0; p < 4; p++)
            *(unsigned long long*)(col_ptr + 2 * p) = acc[p][c];
    }
}

// ---------------- launch ----------------
extern "C" void kernel_launch(void* const* d_in, const int* in_sizes, int n_in,
                              void* d_out, int out_size) {
    const float* x    = (const float*)d_in[0];
    const int*   esrc = (const int*)d_in[1];
    const int*   edst = (const int*)d_in[2];
    const float* ew   = (const float*)d_in[3];
    const float* eps  = (const float*)d_in[4];
    const float* W1   = (const float*)d_in[5];
    const float* b1   = (const float*)d_in[6];
    const float* Wmu  = (const float*)d_in[7];
    const float* bmu  = (const float*)d_in[8];
    const float* Wls  = (const float*)d_in[9];
    const float* bls  = (const float*)d_in[10];

    float* out  = (float*)d_out;
    float* oz   = out;                                   // z        [8192,64]
    float* oadj = out + (size_t)NROW * 64;               // adj      [8192,8192]
    float* omu  = oadj + (size_t)NROW * NROW;            // mu       [8192,64]
    float* ols  = omu + (size_t)NROW * 64;               // logstd   [8192,64]

    cudaFuncSetAttribute(k_zzt, cudaFuncAttributeMaxDynamicSharedMemorySize, 65536);

    k_zero<<<(2 * NROW + 255) / 256, 256>>>();
    k_count<<<NE / 256, 256>>>(esrc);
    k_scan<<<1, 1024>>>();
    k_scatter<<<NE / 256, 256>>>(esrc, edst, ew);
    k_gemm1<<<dim3(4, 64), 256>>>(x, W1, b1);
    k_spmm1<<<NROW, 128>>>();
    k_gemm2<<<dim3(2, 64), 256>>>(Wmu, bmu, Wls, bls);
    k_spmm2<<<NROW, 128>>>(eps, oz, omu, ols);
    k_zzt<<<64 * 65 / 2, 256, 65536>>>(oadj);
}

// round 6
// speedup vs baseline: 1.3619x; 1.3619x over previous
#include <cuda_runtime.h>
#include <cuda_bf16.h>
#include <cstdint>
#include <math.h>

#define NROW 8192
#define NE   262144

// ---------------- scratch (static device arrays; no allocation) ----------------
__device__ __align__(16) float g_t[NROW * 256];   // x@W1+b1
__device__ __align__(16) float g_h[NROW * 256];   // tanh(spmm(t))
__device__ __align__(16) float g_g[NROW * 128];   // h@[Wmu|Wls]+b
__device__ __align__(16) __nv_bfloat16 g_zhi[NROW * 64];
__device__ __align__(16) __nv_bfloat16 g_zlo[NROW * 64];
__device__ int   g_counts[NROW];
__device__ int   g_cursor[NROW];
__device__ int   g_rowptr[NROW + 1];
__device__ int   g_cols[NE];
__device__ __align__(16) float g_wts[NE];

// ---------------- packed f32x2 helpers (bit-exact fp32, 2x FFMA rate) ----------
__device__ __forceinline__ unsigned long long dup2(float x) {
    unsigned long long u;
    asm("mov.b64 %0, {%1, %1};" : "=l"(u) : "f"(x));
    return u;
}
__device__ __forceinline__ void ffma2(unsigned long long& acc, unsigned long long a,
                                      unsigned long long b) {
    asm("fma.rn.f32x2 %0, %1, %2, %0;" : "+l"(acc) : "l"(a), "l"(b));
}
__device__ __forceinline__ float2 unpack2(unsigned long long u) {
    float2 v;
    asm("mov.b64 {%0, %1}, %2;" : "=f"(v.x), "=f"(v.y) : "l"(u));
    return v;
}

// ---------------- warp MMA helpers (plain-target: ldmatrix + mma.sync) ----------
__device__ __forceinline__ uint32_t smem_u32(const void* p) {
    uint32_t a;
    asm("{ .reg .u64 t; cvta.to.shared.u64 t, %1; cvt.u32.u64 %0, t; }" : "=r"(a) : "l"(p));
    return a;
}
__device__ __forceinline__ void ldsm4(uint32_t& r0, uint32_t& r1, uint32_t& r2, uint32_t& r3,
                                      uint32_t addr) {
    asm volatile("ldmatrix.sync.aligned.m8n8.x4.shared.b16 {%0,%1,%2,%3}, [%4];"
                 : "=r"(r0), "=r"(r1), "=r"(r2), "=r"(r3) : "r"(addr));
}
__device__ __forceinline__ void mma16816(float* c, const uint32_t* a, const uint32_t* b) {
    asm volatile(
        "mma.sync.aligned.m16n8k16.row.col.f32.bf16.bf16.f32 "
        "{%0,%1,%2,%3}, {%4,%5,%6,%7}, {%8,%9}, {%0,%1,%2,%3};"
        : "+f"(c[0]), "+f"(c[1]), "+f"(c[2]), "+f"(c[3])
        : "r"(a[0]), "r"(a[1]), "r"(a[2]), "r"(a[3]), "r"(b[0]), "r"(b[1]));
}
#define SWZ128(x) ((x) ^ (((x) >> 3) & 0x70))

// ---------------- CSR build ----------------
__global__ void k_zero() {
    int i = blockIdx.x * 256 + threadIdx.x;
    if (i < NROW) g_counts[i] = 0;
    else g_cursor[i - NROW] = 0;
}

__global__ void k_count(const int* __restrict__ src) {
    int i = blockIdx.x * 256 + threadIdx.x;
    if (i < NE) atomicAdd(&g_counts[src[i]], 1);
}

__global__ void k_scan() {  // one block, 1024 threads, 8 counts each
    __shared__ int sh[1024];
    int tid = threadIdx.x;
    int c[8]; int s = 0;
#pragma unroll
    for (int i = 0; i < 8; i++) { c[i] = g_counts[tid * 8 + i]; s += c[i]; }
    sh[tid] = s;
    __syncthreads();
    for (int off = 1; off < 1024; off <<= 1) {
        int v = (tid >= off) ? sh[tid - off] : 0;
        __syncthreads();
        sh[tid] += v;
        __syncthreads();
    }
    int base = sh[tid] - s;  // exclusive prefix
#pragma unroll
    for (int i = 0; i < 8; i++) { g_rowptr[tid * 8 + i] = base; base += c[i]; }
    if (tid == 1023) g_rowptr[NROW] = sh[1023];
}

__global__ void k_scatter(const int* __restrict__ src, const int* __restrict__ dst,
                          const float* __restrict__ w) {
    int i = blockIdx.x * 256 + threadIdx.x;
    if (i < NE) {
        int r = src[i];
        int pos = g_rowptr[r] + atomicAdd(&g_cursor[r], 1);
        g_cols[pos] = dst[i];
        g_wts[pos]  = w[i];
    }
}

// ---------------- GEMM1: g_t = x[8192,512] @ W1[512,256] + b1 ----------------
__global__ __launch_bounds__(256) void k_gemm1(const float* __restrict__ x,
                                               const float* __restrict__ W1,
                                               const float* __restrict__ b1) {
    __shared__ float As[16 * 128];
    __shared__ float Bs[16 * 64];
    const int bm = blockIdx.y, bn = blockIdx.x;
    const int tid = threadIdx.x;
    const int ty = tid >> 4, tx = tid & 15;
    const int row0 = ty * 8, col0 = tx * 4;

    unsigned long long acc[4][4];
    {
        float4 bv = *(const float4*)(b1 + bn * 64 + col0);
        unsigned long long ix = dup2(bv.x), iy = dup2(bv.y), iz = dup2(bv.z), iw = dup2(bv.w);
#pragma unroll
        for (int p = 0; p < 4; p++) { acc[p][0] = ix; acc[p][1] = iy; acc[p][2] = iz; acc[p][3] = iw; }
    }

    for (int kt = 0; kt < 32; kt++) {
#pragma unroll
        for (int pass = 0; pass < 2; pass++) {
            int idx = tid + pass * 256;
            int ar = idx >> 2;
            int kq = idx & 3;
            float4 v = *(const float4*)(x + (size_t)(bm * 128 + ar) * 512 + kt * 16 + kq * 4);
            int rs = ar ^ (kq << 3);
            As[(kq * 4 + 0) * 128 + rs] = v.x;
            As[(kq * 4 + 1) * 128 + rs] = v.y;
            As[(kq * 4 + 2) * 128 + rs] = v.z;
            As[(kq * 4 + 3) * 128 + rs] = v.w;
        }
        {
            int kr = tid >> 4, cq = tid & 15;
            *(float4*)&Bs[kr * 64 + cq * 4] =
                *(const float4*)(W1 + (size_t)(kt * 16 + kr) * 256 + bn * 64 + cq * 4);
        }
        __syncthreads();
#pragma unroll
        for (int k = 0; k < 16; k++) {
            const float* ab = &As[k * 128 + (row0 ^ ((k >> 2) << 3))];
            unsigned long long a0 = *(const unsigned long long*)(ab + 0);
            unsigned long long a1 = *(const unsigned long long*)(ab + 2);
            unsigned long long a2 = *(const unsigned long long*)(ab + 4);
            unsigned long long a3 = *(const unsigned long long*)(ab + 6);
            float4 b = *(const float4*)&Bs[k * 64 + col0];
            unsigned long long bx = dup2(b.x), by = dup2(b.y), bz = dup2(b.z), bw = dup2(b.w);
            ffma2(acc[0][0], a0, bx); ffma2(acc[0][1], a0, by); ffma2(acc[0][2], a0, bz); ffma2(acc[0][3], a0, bw);
            ffma2(acc[1][0], a1, bx); ffma2(acc[1][1], a1, by); ffma2(acc[1][2], a1, bz); ffma2(acc[1][3], a1, bw);
            ffma2(acc[2][0], a2, bx); ffma2(acc[2][1], a2, by); ffma2(acc[2][2], a2, bz); ffma2(acc[2][3], a2, bw);
            ffma2(acc[3][0], a3, bx); ffma2(acc[3][1], a3, by); ffma2(acc[3][2], a3, bz); ffma2(acc[3][3], a3, bw);
        }
        __syncthreads();
    }
    float* Cp = g_t + (size_t)(bm * 128 + row0) * 256 + bn * 64 + col0;
#pragma unroll
    for (int p = 0; p < 4; p++) {
        float2 t0 = unpack2(acc[p][0]), t1 = unpack2(acc[p][1]);
        float2 t2 = unpack2(acc[p][2]), t3 = unpack2(acc[p][3]);
        *(float4*)(Cp + (size_t)(2 * p) * 256)     = make_float4(t0.x, t1.x, t2.x, t3.x);
        *(float4*)(Cp + (size_t)(2 * p + 1) * 256) = make_float4(t0.y, t1.y, t2.y, t3.y);
    }
}

// ---------------- GEMM2: g_g = g_h[8192,256] @ [Wmu|Wls][256,128] + [bmu|bls] ----
__global__ __launch_bounds__(256) void k_gemm2(const float* __restrict__ Wmu,
                                               const float* __restrict__ bmu,
                                               const float* __restrict__ Wls,
                                               const float* __restrict__ bls) {
    __shared__ float As[16 * 128];
    __shared__ float Bs[16 * 64];
    const int bm = blockIdx.y, bn = blockIdx.x;
    const float* W = (bn == 0) ? Wmu : Wls;
    const float* bb = (bn == 0) ? bmu : bls;
    const int tid = threadIdx.x;
    const int ty = tid >> 4, tx = tid & 15;
    const int row0 = ty * 8, col0 = tx * 4;

    unsigned long long acc[4][4];
    {
        float4 bv = *(const float4*)(bb + col0);
        unsigned long long ix = dup2(bv.x), iy = dup2(bv.y), iz = dup2(bv.z), iw = dup2(bv.w);
#pragma unroll
        for (int p = 0; p < 4; p++) { acc[p][0] = ix; acc[p][1] = iy; acc[p][2] = iz; acc[p][3] = iw; }
    }

    for (int kt = 0; kt < 16; kt++) {
#pragma unroll
        for (int pass = 0; pass < 2; pass++) {
            int idx = tid + pass * 256;
            int ar = idx >> 2;
            int kq = idx & 3;
            float4 v = *(const float4*)(g_h + (size_t)(bm * 128 + ar) * 256 + kt * 16 + kq * 4);
            int rs = ar ^ (kq << 3);
            As[(kq * 4 + 0) * 128 + rs] = v.x;
            As[(kq * 4 + 1) * 128 + rs] = v.y;
            As[(kq * 4 + 2) * 128 + rs] = v.z;
            As[(kq * 4 + 3) * 128 + rs] = v.w;
        }
        {
            int kr = tid >> 4, cq = tid & 15;
            *(float4*)&Bs[kr * 64 + cq * 4] =
                *(const float4*)(W + (size_t)(kt * 16 + kr) * 64 + cq * 4);
        }
        __syncthreads();
#pragma unroll
        for (int k = 0; k < 16; k++) {
            const float* ab = &As[k * 128 + (row0 ^ ((k >> 2) << 3))];
            unsigned long long a0 = *(const unsigned long long*)(ab + 0);
            unsigned long long a1 = *(const unsigned long long*)(ab + 2);
            unsigned long long a2 = *(const unsigned long long*)(ab + 4);
            unsigned long long a3 = *(const unsigned long long*)(ab + 6);
            float4 b = *(const float4*)&Bs[k * 64 + col0];
            unsigned long long bx = dup2(b.x), by = dup2(b.y), bz = dup2(b.z), bw = dup2(b.w);
            ffma2(acc[0][0], a0, bx); ffma2(acc[0][1], a0, by); ffma2(acc[0][2], a0, bz); ffma2(acc[0][3], a0, bw);
            ffma2(acc[1][0], a1, bx); ffma2(acc[1][1], a1, by); ffma2(acc[1][2], a1, bz); ffma2(acc[1][3], a1, bw);
            ffma2(acc[2][0], a2, bx); ffma2(acc[2][1], a2, by); ffma2(acc[2][2], a2, bz); ffma2(acc[2][3], a2, bw);
            ffma2(acc[3][0], a3, bx); ffma2(acc[3][1], a3, by); ffma2(acc[3][2], a3, bz); ffma2(acc[3][3], a3, bw);
        }
        __syncthreads();
    }
    float* Cp = g_g + (size_t)(bm * 128 + row0) * 128 + bn * 64 + col0;
#pragma unroll
    for (int p = 0; p < 4; p++) {
        float2 t0 = unpack2(acc[p][0]), t1 = unpack2(acc[p][1]);
        float2 t2 = unpack2(acc[p][2]), t3 = unpack2(acc[p][3]);
        *(float4*)(Cp + (size_t)(2 * p) * 128)     = make_float4(t0.x, t1.x, t2.x, t3.x);
        *(float4*)(Cp + (size_t)(2 * p + 1) * 128) = make_float4(t0.y, t1.y, t2.y, t3.y);
    }
}

// ---------------- SpMM1 + tanh ----------------
__global__ void k_spmm1() {
    int r = blockIdx.x, tid = threadIdx.x;
    int s = g_rowptr[r], e = g_rowptr[r + 1];
    const float2* T = (const float2*)g_t;
    float2 acc = make_float2(0.f, 0.f);
    int p = s;
    for (; p + 4 <= e; p += 4) {
        int   c0 = g_cols[p], c1 = g_cols[p + 1], c2 = g_cols[p + 2], c3 = g_cols[p + 3];
        float w0 = g_wts[p], w1 = g_wts[p + 1], w2 = g_wts[p + 2], w3 = g_wts[p + 3];
        float2 v0 = T[c0 * 128 + tid];
        float2 v1 = T[c1 * 128 + tid];
        float2 v2 = T[c2 * 128 + tid];
        float2 v3 = T[c3 * 128 + tid];
        acc.x = fmaf(w0, v0.x, acc.x); acc.y = fmaf(w0, v0.y, acc.y);
        acc.x = fmaf(w1, v1.x, acc.x); acc.y = fmaf(w1, v1.y, acc.y);
        acc.x = fmaf(w2, v2.x, acc.x); acc.y = fmaf(w2, v2.y, acc.y);
        acc.x = fmaf(w3, v3.x, acc.x); acc.y = fmaf(w3, v3.y, acc.y);
    }
    for (; p < e; p++) {
        int c = g_cols[p]; float w = g_wts[p];
        float2 v = T[c * 128 + tid];
        acc.x = fmaf(w, v.x, acc.x); acc.y = fmaf(w, v.y, acc.y);
    }
    ((float2*)g_h)[r * 128 + tid] = make_float2(tanhf(acc.x), tanhf(acc.y));
}

// ---------------- SpMM2 + reparameterize + bf16 split ----------------
__global__ void k_spmm2(const float* __restrict__ eps, float* __restrict__ oz,
                        float* __restrict__ omu, float* __restrict__ ols) {
    int r = blockIdx.x, tid = threadIdx.x;
    int s = g_rowptr[r], e = g_rowptr[r + 1];
    float acc = 0.f;
    int p = s;
    for (; p + 4 <= e; p += 4) {
        int   c0 = g_cols[p], c1 = g_cols[p + 1], c2 = g_cols[p + 2], c3 = g_cols[p + 3];
        float w0 = g_wts[p], w1 = g_wts[p + 1], w2 = g_wts[p + 2], w3 = g_wts[p + 3];
        float v0 = g_g[c0 * 128 + tid];
        float v1 = g_g[c1 * 128 + tid];
        float v2 = g_g[c2 * 128 + tid];
        float v3 = g_g[c3 * 128 + tid];
        acc = fmaf(w0, v0, acc); acc = fmaf(w1, v1, acc);
        acc = fmaf(w2, v2, acc); acc = fmaf(w3, v3, acc);
    }
    for (; p < e; p++) acc = fmaf(g_wts[p], g_g[g_cols[p] * 128 + tid], acc);
    __shared__ float sm[128];
    sm[tid] = acc;
    __syncthreads();
    if (tid < 64) {
        float mu = sm[tid], ls = sm[tid + 64];
        float z = fmaf(eps[r * 64 + tid], expf(ls), mu);
        omu[r * 64 + tid] = mu;
        ols[r * 64 + tid] = ls;
        oz[r * 64 + tid]  = z;
        __nv_bfloat16 zh = __float2bfloat16(z);
        g_zhi[r * 64 + tid] = zh;
        g_zlo[r * 64 + tid] = __float2bfloat16(z - __bfloat162float(zh));
    }
}

// ---------------- z @ z^T via mma.sync bf16 split: C = ZhiZhi' + ZhiZlo' + ZloZhi'
// Full grid 64x64, 128x128 tile/CTA, 8 warps = 4(m) x 2(n), warp tile 32x64.
// SMEM: 4 tiles (Ahi,Alo,Bhi,Blo) of 128 rows x 128B (SW128-swizzled), 64KB.
#define ZZT_SMEM (4 * 16384)
__global__ __launch_bounds__(256, 2) void k_zzt_mma(float* __restrict__ C) {
    extern __shared__ __align__(1024) char smem[];
    char* tAhi = smem;
    char* tAlo = smem + 16384;
    char* tBhi = smem + 32768;
    char* tBlo = smem + 49152;
    const int bi = blockIdx.y, bj = blockIdx.x;
    const int tid = threadIdx.x, wid = tid >> 5, lid = tid & 31;

    // Load 4 tiles: 128 rows x 64 bf16 = 1024 uint4 per tile, coalesced, swizzled store
    {
        const uint4* ghi_a = (const uint4*)(g_zhi + (size_t)bi * 128 * 64);
        const uint4* glo_a = (const uint4*)(g_zlo + (size_t)bi * 128 * 64);
        const uint4* ghi_b = (const uint4*)(g_zhi + (size_t)bj * 128 * 64);
        const uint4* glo_b = (const uint4*)(g_zlo + (size_t)bj * 128 * 64);
#pragma unroll
        for (int p = 0; p < 4; p++) {
            int idx = tid + p * 256;               // 0..1023
            int row = idx >> 3, q = idx & 7;       // q: 16B chunk
            uint32_t off = SWZ128((uint32_t)(row * 128 + q * 16));
            *(uint4*)(tAhi + off) = ghi_a[idx];
            *(uint4*)(tAlo + off) = glo_a[idx];
            *(uint4*)(tBhi + off) = ghi_b[idx];
            *(uint4*)(tBlo + off) = glo_b[idx];
        }
    }
    __syncthreads();

    const int wm = wid >> 1, wn = wid & 1;
    const uint32_t sAhi = smem_u32(tAhi), sAlo = smem_u32(tAlo);
    const uint32_t sBhi = smem_u32(tBhi), sBlo = smem_u32(tBlo);

    float acc[2][8][4];
#pragma unroll
    for (int mt = 0; mt < 2; mt++)
#pragma unroll
        for (int nt = 0; nt < 8; nt++)
#pragma unroll
            for (int r = 0; r < 4; r++) acc[mt][nt][r] = 0.f;

    const int l7 = lid & 7, g2 = lid >> 3;         // g2: which of 4 ldmatrix sub-matrices

#pragma unroll
    for (int ks = 0; ks < 4; ks++) {               // K=64, 16 per step
        // A fragments: mt tiles rows wm*32 + mt*16; sub-matrix mapping:
        //   g2&1 -> +8 rows, g2>>1 -> second 16B k-chunk
        uint32_t ahi[2][4], alo[2][4];
#pragma unroll
        for (int mt = 0; mt < 2; mt++) {
            int row = wm * 32 + mt * 16 + ((g2 & 1) << 3) + l7;
            int q   = ks * 2 + (g2 >> 1);
            uint32_t off = SWZ128((uint32_t)(row * 128 + q * 16));
            ldsm4(ahi[mt][0], ahi[mt][1], ahi[mt][2], ahi[mt][3], sAhi + off);
            ldsm4(alo[mt][0], alo[mt][1], alo[mt][2], alo[mt][3], sAlo + off);
        }
        // B fragments: pairs of n8 tiles; sub-matrix mapping:
        //   g2>>1 -> +8 n-rows (second tile), g2&1 -> second 16B k-chunk
#pragma unroll
        for (int ntp = 0; ntp < 4; ntp++) {
            int nrow = wn * 64 + ntp * 16 + ((g2 >> 1) << 3) + l7;
            int q    = ks * 2 + (g2 & 1);
            uint32_t off = SWZ128((uint32_t)(nrow * 128 + q * 16));
            uint32_t bh[4], bl[4];
            ldsm4(bh[0], bh[1], bh[2], bh[3], sBhi + off);
            ldsm4(bl[0], bl[1], bl[2], bl[3], sBlo + off);
            int nt0 = ntp * 2, nt1 = ntp * 2 + 1;
#pragma unroll
            for (int mt = 0; mt < 2; mt++) {
                mma16816(acc[mt][nt0], ahi[mt], bh + 0);   // hi*hi
                mma16816(acc[mt][nt1], ahi[mt], bh + 2);
                mma16816(acc[mt][nt0], ahi[mt], bl + 0);   // hi*lo
                mma16816(acc[mt][nt1], ahi[mt], bl + 2);
                mma16816(acc[mt][nt0], alo[mt], bh + 0);   // lo*hi
                mma16816(acc[mt][nt1], alo[mt], bh + 2);
            }
        }
    }

    // Epilogue: fragment-direct stores (8B per lane per tile-row)
    const int lg = lid >> 2, lt = lid & 3;
#pragma unroll
    for (int mt = 0; mt < 2; mt++) {
        size_t r0 = (size_t)(bi * 128 + wm * 32 + mt * 16 + lg);
        float* row0 = C + r0 * NROW + bj * 128 + wn * 64 + 2 * lt;
        float* row1 = row0 + 8 * (size_t)NROW;
#pragma unroll
        for (int nt = 0; nt < 8; nt++) {
            *(float2*)(row0 + nt * 8) = make_float2(acc[mt][nt][0], acc[mt][nt][1]);
            *(float2*)(row1 + nt * 8) = make_float2(acc[mt][nt][2], acc[mt][nt][3]);
        }
    }
}

// ---------------- launch ----------------
extern "C" void kernel_launch(void* const* d_in, const int* in_sizes, int n_in,
                              void* d_out, int out_size) {
    const float* x    = (const float*)d_in[0];
    const int*   esrc = (const int*)d_in[1];
    const int*   edst = (const int*)d_in[2];
    const float* ew   = (const float*)d_in[3];
    const float* eps  = (const float*)d_in[4];
    const float* W1   = (const float*)d_in[5];
    const float* b1   = (const float*)d_in[6];
    const float* Wmu  = (const float*)d_in[7];
    const float* bmu  = (const float*)d_in[8];
    const float* Wls  = (const float*)d_in[9];
    const float* bls  = (const float*)d_in[10];

    float* out  = (float*)d_out;
    float* oz   = out;                                   // z        [8192,64]
    float* oadj = out + (size_t)NROW * 64;               // adj      [8192,8192]
    float* omu  = oadj + (size_t)NROW * NROW;            // mu       [8192,64]
    float* ols  = omu + (size_t)NROW * 64;               // logstd   [8192,64]

    cudaFuncSetAttribute(k_zzt_mma, cudaFuncAttributeMaxDynamicSharedMemorySize, ZZT_SMEM);

    k_zero<<<(2 * NROW + 255) / 256, 256>>>();
    k_count<<<NE / 256, 256>>>(esrc);
    k_scan<<<1, 1024>>>();
    k_scatter<<<NE / 256, 256>>>(esrc, edst, ew);
    k_gemm1<<<dim3(4, 64), 256>>>(x, W1, b1);
    k_spmm1<<<NROW, 128>>>();
    k_gemm2<<<dim3(2, 64), 256>>>(Wmu, bmu, Wls, bls);
    k_spmm2<<<NROW, 128>>>(eps, oz, omu, ols);
    k_zzt_mma<<<dim3(64, 64), 256, ZZT_SMEM>>>(oadj);
}